// round 15
// baseline (speedup 1.0000x reference)
#include <cuda_runtime.h>
#include <cuda_fp16.h>
#include <cstdint>

#define H 256
#define NMAX 20000
#define EMAX 320000
#define GMAX 1000
#define DIS 384

typedef unsigned int u32;
typedef unsigned short us;

// ============================ helpers ============================
__device__ __forceinline__ u32 smem_u32(const void* p) {
    u32 a;
    asm("{ .reg .u64 t; cvta.to.shared.u64 t, %1; cvt.u32.u64 %0, t; }" : "=r"(a) : "l"(p));
    return a;
}
__device__ __forceinline__ void cpa(u32 dst, const void* src, int sz) {
    asm volatile("cp.async.cg.shared.global [%0], [%1], 16, %2;"
                 :: "r"(dst), "l"(src), "r"(sz) : "memory");
}
__device__ __forceinline__ void cpcommit() {
    asm volatile("cp.async.commit_group;" ::: "memory");
}
template <int N>
__device__ __forceinline__ void cpwait() {
    asm volatile("cp.async.wait_group %0;" :: "n"(N) : "memory");
}
__device__ __forceinline__ void ldmx4(u32* r, u32 addr) {
    asm volatile("ldmatrix.sync.aligned.m8n8.x4.shared.b16 {%0,%1,%2,%3}, [%4];"
                 : "=r"(r[0]), "=r"(r[1]), "=r"(r[2]), "=r"(r[3]) : "r"(addr));
}
// m16n8k16 fp16 mma, fp32 accum (arch-neutral HMMA path)
__device__ __forceinline__ void mma16816(float* c, const u32* a, const u32* b) {
    asm volatile(
        "mma.sync.aligned.m16n8k16.row.col.f32.f16.f16.f32 "
        "{%0,%1,%2,%3},{%4,%5,%6,%7},{%8,%9},{%0,%1,%2,%3};"
        : "+f"(c[0]), "+f"(c[1]), "+f"(c[2]), "+f"(c[3])
        : "r"(a[0]), "r"(a[1]), "r"(a[2]), "r"(a[3]), "r"(b[0]), "r"(b[1]));
}
// vector fp32 reduction (PTX ISA 8.1+, sm_90+; validated rounds 10-14)
__device__ __forceinline__ void redv2(float* addr, float a, float b) {
    asm volatile("red.global.add.v2.f32 [%0], {%1, %2};"
                 :: "l"(addr), "f"(a), "f"(b) : "memory");
}
__device__ __forceinline__ float dsilu(float x) {
    return __fdividef(x, 1.0f + __expf(-x));
}
__device__ __forceinline__ us cvt1(float v) {
    __half h = __float2half(v);
    return *reinterpret_cast<us*>(&h);
}

// ============================ device scratch ============================
__device__ int g_is64;
__device__ int g_src[EMAX];
__device__ int g_dst[EMAX];
__device__ int g_e2g[EMAX];
__device__ float g_PQS[(size_t)NMAX * 768];  // P | Q | S per row
__device__ float g_R[GMAX * H];
__device__ float g_sums[NMAX * H];
__device__ float g_cnt[NMAX];
__device__ float g_rcnt[NMAX];
// fp16 activations
__device__ us g_hs[NMAX * H];
__device__ us g_e1[(size_t)EMAX * H];
__device__ us g_sum16[NMAX * H];
__device__ us g_t1[NMAX * H];
// fp16 transposed weights Bt[n][k]
__device__ us g_wPQS[768 * H];
__device__ us g_wF[H * DIS];   // femb weights, K PERMUTED: k' = d*128 + 2f + s
__device__ us g_w2[H * H];
__device__ us g_wN[H * H];
__device__ us g_wO[H * H];

// ============================ small kernels ============================
__global__ void detect_k(const void* eidx, int E) {
    __shared__ int any;
    if (threadIdx.x == 0) any = 0;
    __syncthreads();
    const int* w = (const int*)eidx;
    int lim = 2048 < (E - 1) ? 2048 : (E - 1);
    for (int i = threadIdx.x; i < lim; i += blockDim.x)
        if (w[2 * i + 1] != 0) any = 1;
    __syncthreads();
    if (threadIdx.x == 0) g_is64 = (any == 0) ? 1 : 0;
}

__global__ void convert_k(const void* eidx, const void* e2g, int E) {
    int i = blockIdx.x * blockDim.x + threadIdx.x;
    if (i >= E) return;
    int s;
    if (g_is64) {
        const long long* p = (const long long*)eidx;
        const long long* q = (const long long*)e2g;
        s = (int)p[i];
        g_dst[i] = (int)p[(size_t)E + i];
        g_e2g[i] = (int)q[i];
    } else {
        const int* p = (const int*)eidx;
        const int* q = (const int*)e2g;
        s = p[i];
        g_dst[i] = p[E + i];
        g_e2g[i] = q[i];
    }
    g_src[i] = s;
    atomicAdd(&g_cnt[s], 1.0f);
}

__global__ void rcnt_k(int Nn) {
    int i = blockIdx.x * blockDim.x + threadIdx.x;
    if (i < Nn) g_rcnt[i] = 1.0f / fmaxf(g_cnt[i], 1.0f);
}

__global__ __launch_bounds__(256) void ln_k(const float* __restrict__ x,
                                            const float* __restrict__ gm,
                                            const float* __restrict__ bt) {
    int row = blockIdx.x;
    int c = threadIdx.x;
    float v = x[(size_t)row * H + c];
    float s = v, ss = v * v;
#pragma unroll
    for (int o = 16; o; o >>= 1) {
        s  += __shfl_xor_sync(0xffffffffu, s, o);
        ss += __shfl_xor_sync(0xffffffffu, ss, o);
    }
    __shared__ float as[8], bs[8];
    if ((c & 31) == 0) { as[c >> 5] = s; bs[c >> 5] = ss; }
    __syncthreads();
    s = 0.f; ss = 0.f;
#pragma unroll
    for (int i = 0; i < 8; i++) { s += as[i]; ss += bs[i]; }
    float mu  = s * (1.0f / H);
    float var = ss * (1.0f / H) - mu * mu;
    float inv = rsqrtf(var + 1e-5f);
    g_hs[(size_t)row * H + c] = cvt1((v - mu) * inv * gm[c] + bt[c]);
}

__global__ __launch_bounds__(256) void lat_k(const float* __restrict__ L,
                                             const float* __restrict__ We1,
                                             const float* __restrict__ be1) {
    int g = blockIdx.x;
    __shared__ float ll[9];
    if (threadIdx.x < 9) {
        int i = threadIdx.x / 3, k = threadIdx.x % 3;
        const float* Lg = L + g * 9;
        ll[threadIdx.x] = Lg[i * 3 + 0] * Lg[k * 3 + 0] +
                          Lg[i * 3 + 1] * Lg[k * 3 + 1] +
                          Lg[i * 3 + 2] * Lg[k * 3 + 2];
    }
    __syncthreads();
    int c = threadIdx.x;
    float a = be1[c];
#pragma unroll
    for (int p = 0; p < 9; p++) a += ll[p] * We1[(512 + p) * H + c];
    g_R[g * H + c] = a;
}

// merged weight transpose -> fp16 for all 7 segments: Bt[n][k] = fp16(W[k][n])
// Segment 3 (femb) applies the K-permutation k' = d*128 + 2f + s
// (orig row = s*192 + d*64 + f) so in-GEMM generation order matches.
__global__ void twall_k(const float* __restrict__ We1, const float* __restrict__ We2,
                        const float* __restrict__ Wn1, const float* __restrict__ Wn2,
                        us* __restrict__ wPQS, us* __restrict__ wF,
                        us* __restrict__ w2, us* __restrict__ wN, us* __restrict__ wO) {
    const int seg = blockIdx.y;
    const int idx = blockIdx.x * 256 + threadIdx.x;
    const float* W;
    int K;
    us* o;
    switch (seg) {
        case 0: W = We1;           K = 256; o = wPQS;           break;  // P
        case 1: W = We1 + 256 * H; K = 256; o = wPQS + 256 * H; break;  // Q
        case 2: W = Wn1;           K = 256; o = wPQS + 512 * H; break;  // S
        case 3: W = We1 + 521 * H; K = 384; o = wF;             break;  // femb (permuted)
        case 4: W = We2;           K = 256; o = w2;             break;
        case 5: W = Wn1 + 256 * H; K = 256; o = wN;             break;
        default: W = Wn2;          K = 256; o = wO;             break;
    }
    if (idx >= 256 * K) return;
    int n = idx / K, k = idx % K;
    if (seg == 3) {
        int d = k >> 7, rr = k & 127, f = rr >> 1, s = rr & 1;
        k = s * 192 + d * 64 + f;  // original row in We1[521:905]
    }
    o[idx] = cvt1(W[(size_t)k * 256 + n]);
}

__global__ void cvt_k(const float* __restrict__ in, us* __restrict__ o, int n) {
    int i = blockIdx.x * blockDim.x + threadIdx.x;
    if (i < n) o[i] = cvt1(in[i]);
}

// ============================ HMMA GEMM (fp16, M64xN256 tiles) ==============
// Block tile 64(M) x 256(N), 8 warps (2M x 4N), warp tile 32x64, 2 CTAs/SM.
// Full-N tiles: A is streamed exactly ONCE per GEMM.
// A, B single fp16 planes; 1 MMA per (mt,nt) k-step; fp32 accum.
// cp.async TRIPLE-buffered KC=32 chunks; fragments via ldmatrix.x4.
// GEN=1 (MODE 1): A chunks generated in-kernel (sinusoid embedding, permuted K).
// MODE 0: Cf[row*ldx+col] = acc
// MODE 1: Ch = fp16(silu(acc + P[src] + Q[dst] + R[e2g]))
// MODE 2: red.v2(Cf[src[row]], silu(acc + bias))
// MODE 3: Ch = fp16(silu(rowScale[row]*acc + addRow + bias))
// MODE 4: Cf = addRow + silu(acc + bias)
#define PLANE_A 5120      // 64 * 20 words * 4B
#define PLANE_B 20480     // 256 * 20 words * 4B
#define BUFB    25600     // A + B
#define SMEM_TOTAL 76800  // 3 buffers

template <int MODE, int GEN>
__global__ __launch_bounds__(256, 2) void tgemm(
    const us* __restrict__ A, const us* __restrict__ B,
    int M, int K, int ldx,
    const int* __restrict__ src, const int* __restrict__ dst,
    const int* __restrict__ e2g,
    const float* __restrict__ Pm, const float* __restrict__ Qm,
    const float* __restrict__ Rm,
    const float* __restrict__ bias, const float* __restrict__ rowScale,
    const float* __restrict__ addRow,
    const float* __restrict__ fdp,
    float* __restrict__ Cf, us* __restrict__ Ch) {
    extern __shared__ char smem[];
    const u32 sb = smem_u32(smem);
    const int tid  = threadIdx.x;
    const int lane = tid & 31;
    const int wid  = tid >> 5;
    const int g = lane >> 2, q = lane & 3;
    const int row0  = blockIdx.y * 64;
    const int nbase = blockIdx.x * 256;
    const int mrow0  = (wid & 1) * 32;
    const int nwarp0 = (wid >> 1) * 64;

    const int rowin = lane & 7;
    const int msel  = lane >> 3;
    u32 offA[2];  // [mt]
#pragma unroll
    for (int mt = 0; mt < 2; mt++)
        offA[mt] = (u32)((mrow0 + mt * 16 + rowin + (msel & 1) * 8) * 80 +
                         (msel >> 1) * 16);
    const u32 offB = (u32)(PLANE_A + (nwarp0 + (msel >> 1) * 8 + rowin) * 80 +
                           (msel & 1) * 16);

    float acc[2][8][4];
#pragma unroll
    for (int a = 0; a < 2; a++)
#pragma unroll
        for (int b = 0; b < 8; b++)
#pragma unroll
            for (int c = 0; c < 4; c++) acc[a][b][c] = 0.0f;

    const int nch = K >> 5;

    auto issue = [&](int ch, int buf) {
        char* b0p = smem + buf * BUFB;
        const u32 b0 = sb + buf * BUFB;
        if (GEN) {
            // generate A chunk: 64 edges x 32 halves (tid < 128 active).
            // chunk ch: d = ch/4, freqs [(ch%4)*16, +16), sin/cos interleaved.
            if (tid < 128) {
                const int e = tid >> 1;
                const int p = tid & 1;
                const int d = ch >> 2;
                const int f0 = ((ch & 3) << 4) + (p << 3);
                const int ge = row0 + e;
                float x = (ge < M) ? fdp[(size_t)ge * 3 + d] : 0.0f;
                float y = x * (float)f0;
                y -= floorf(y);                       // range-reduce: frac(x*f)
                float sf, cf, s1, c1;
                __sincosf(6.28318530717958647692f * y, &sf, &cf);
                __sincosf(6.28318530717958647692f * x, &s1, &c1);
                u32 w[8];
#pragma unroll
                for (int i = 0; i < 8; i++) {
                    asm("cvt.rn.f16x2.f32 %0, %1, %2;" : "=r"(w[i]) : "f"(cf), "f"(sf));
                    float ns = sf * c1 + cf * s1;
                    float nc = cf * c1 - sf * s1;
                    sf = ns;
                    cf = nc;
                }
                uint4* dst4 = (uint4*)(b0p + e * 80 + p * 32);
                dst4[0] = make_uint4(w[0], w[1], w[2], w[3]);
                dst4[1] = make_uint4(w[4], w[5], w[6], w[7]);
            }
        } else {
            // A: 64 rows x 4 ksegs = 256 cpa, one per thread
            int r = tid >> 2, ksg = tid & 3;
            u32 dstp = b0 + (u32)(r * 80 + ksg * 16);
            int ra = row0 + r;
            int sz = (ra < M) ? 16 : 0;
            if (ra >= M) ra = M - 1;
            cpa(dstp, A + (size_t)ra * K + ch * 32 + ksg * 8, sz);
        }
        // B: 256 rows x 4 ksegs = 1024 cpa, 4 per thread
#pragma unroll
        for (int j = 0; j < 4; j++) {
            int seg = tid + j * 256;
            int r = seg >> 2, ksg = seg & 3;
            u32 dstp = b0 + (u32)(PLANE_A + r * 80 + ksg * 16);
            cpa(dstp, B + (size_t)(nbase + r) * K + ch * 32 + ksg * 8, 16);
        }
        cpcommit();
    };

    issue(0, 0);
    if (nch > 1) issue(1, 1);
    int buf = 0;
    for (int ch = 0; ch < nch; ++ch) {
        if (ch + 2 < nch) issue(ch + 2, (ch + 2) % 3);
        if (ch + 2 < nch)       cpwait<2>();
        else if (ch + 1 < nch)  cpwait<1>();
        else                    cpwait<0>();
        __syncthreads();
        const u32 ab = sb + buf * BUFB;
#pragma unroll
        for (int ks = 0; ks < 2; ks++) {
            u32 afr[2][4];
#pragma unroll
            for (int mt = 0; mt < 2; mt++)
                ldmx4(afr[mt], ab + offA[mt] + ks * 32);
#pragma unroll
            for (int nt2 = 0; nt2 < 4; nt2++) {
                u32 bf[4];
                ldmx4(bf, ab + offB + nt2 * 1280 + ks * 32);
#pragma unroll
                for (int hv = 0; hv < 2; hv++) {
                    const int nt = nt2 * 2 + hv;
#pragma unroll
                    for (int mt = 0; mt < 2; mt++)
                        mma16816(acc[mt][nt], afr[mt], bf + 2 * hv);
                }
            }
        }
        __syncthreads();
        buf = (buf + 1 == 3) ? 0 : buf + 1;
    }

    // ---- epilogue ----
#pragma unroll
    for (int mt = 0; mt < 2; mt++) {
#pragma unroll
        for (int h2 = 0; h2 < 2; h2++) {
            int row = row0 + mrow0 + mt * 16 + g + h2 * 8;
            if (row >= M) continue;
            int s = 0, dn = 0, gg = 0;
            float rsc = 0.0f;
            if (MODE == 1) { s = src[row]; dn = dst[row]; gg = e2g[row]; }
            if (MODE == 2) { s = src[row]; }
            if (MODE == 3) { rsc = rowScale[row]; }
#pragma unroll
            for (int nt = 0; nt < 8; nt++) {
                int col = nbase + nwarp0 + nt * 8 + 2 * q;
                float v0 = acc[mt][nt][h2 * 2 + 0];
                float v1 = acc[mt][nt][h2 * 2 + 1];
                if (MODE == 0) {
                    *(float2*)(Cf + (size_t)row * ldx + col) = make_float2(v0, v1);
                } else if (MODE == 1) {
                    float2 p2 = *(const float2*)(Pm + (size_t)s  * ldx + col);
                    float2 q2 = *(const float2*)(Qm + (size_t)dn * ldx + col);
                    float2 r2 = *(const float2*)(Rm + (size_t)gg * 256 + col);
                    us h0 = cvt1(dsilu(v0 + p2.x + q2.x + r2.x));
                    us h1 = cvt1(dsilu(v1 + p2.y + q2.y + r2.y));
                    *(u32*)(Ch + (size_t)row * 256 + col) = (u32)h0 | ((u32)h1 << 16);
                } else if (MODE == 2) {
                    float2 b2 = *(const float2*)(bias + col);
                    redv2(Cf + (size_t)s * 256 + col,
                          dsilu(v0 + b2.x), dsilu(v1 + b2.y));
                } else if (MODE == 3) {
                    float2 b2 = *(const float2*)(bias + col);
                    float2 a2 = *(const float2*)(addRow + (size_t)row * ldx + col);
                    us h0 = cvt1(dsilu(rsc * v0 + a2.x + b2.x));
                    us h1 = cvt1(dsilu(rsc * v1 + a2.y + b2.y));
                    *(u32*)(Ch + (size_t)row * 256 + col) = (u32)h0 | ((u32)h1 << 16);
                } else {  // MODE 4
                    float2 b2 = *(const float2*)(bias + col);
                    float2 a2 = *(const float2*)(addRow + (size_t)row * 256 + col);
                    *(float2*)(Cf + (size_t)row * 256 + col) =
                        make_float2(a2.x + dsilu(v0 + b2.x), a2.y + dsilu(v1 + b2.y));
                }
            }
        }
    }
}

// ============================ host side ============================
static float *p_PQS, *p_R, *p_sums, *p_cnt, *p_rcnt;
static int *p_src, *p_dst, *p_e2g;
static us *p_hs, *p_e1, *p_sum16, *p_t1;
static us *p_wPQS, *p_wF, *p_w2, *p_wN, *p_wO;
static cudaStream_t s1, s2;
static cudaEvent_t evFork, evS1, evS2;
static bool g_init = false;

static void init_ptrs() {
    if (g_init) return;
    g_init = true;
    cudaGetSymbolAddress((void**)&p_PQS, g_PQS);
    cudaGetSymbolAddress((void**)&p_R, g_R);
    cudaGetSymbolAddress((void**)&p_sums, g_sums);
    cudaGetSymbolAddress((void**)&p_cnt, g_cnt);
    cudaGetSymbolAddress((void**)&p_rcnt, g_rcnt);
    cudaGetSymbolAddress((void**)&p_src, g_src);
    cudaGetSymbolAddress((void**)&p_dst, g_dst);
    cudaGetSymbolAddress((void**)&p_e2g, g_e2g);
    cudaGetSymbolAddress((void**)&p_hs, g_hs);
    cudaGetSymbolAddress((void**)&p_e1, g_e1);
    cudaGetSymbolAddress((void**)&p_sum16, g_sum16);
    cudaGetSymbolAddress((void**)&p_t1, g_t1);
    cudaGetSymbolAddress((void**)&p_wPQS, g_wPQS);
    cudaGetSymbolAddress((void**)&p_wF, g_wF);
    cudaGetSymbolAddress((void**)&p_w2, g_w2);
    cudaGetSymbolAddress((void**)&p_wN, g_wN);
    cudaGetSymbolAddress((void**)&p_wO, g_wO);
    cudaStreamCreateWithFlags(&s1, cudaStreamNonBlocking);
    cudaStreamCreateWithFlags(&s2, cudaStreamNonBlocking);
    cudaEventCreateWithFlags(&evFork, cudaEventDisableTiming);
    cudaEventCreateWithFlags(&evS1, cudaEventDisableTiming);
    cudaEventCreateWithFlags(&evS2, cudaEventDisableTiming);
    cudaFuncSetAttribute(tgemm<0, 0>, cudaFuncAttributeMaxDynamicSharedMemorySize, SMEM_TOTAL);
    cudaFuncSetAttribute(tgemm<1, 1>, cudaFuncAttributeMaxDynamicSharedMemorySize, SMEM_TOTAL);
    cudaFuncSetAttribute(tgemm<2, 0>, cudaFuncAttributeMaxDynamicSharedMemorySize, SMEM_TOTAL);
    cudaFuncSetAttribute(tgemm<3, 0>, cudaFuncAttributeMaxDynamicSharedMemorySize, SMEM_TOTAL);
    cudaFuncSetAttribute(tgemm<4, 0>, cudaFuncAttributeMaxDynamicSharedMemorySize, SMEM_TOTAL);
}
namespace {
struct Boot {
    Boot() { init_ptrs(); }
};
static Boot boot_;
}  // namespace

extern "C" void kernel_launch(void* const* d_in, const int* in_sizes, int n_in,
                              void* d_out, int out_size) {
    init_ptrs();
    const float* nf  = (const float*)d_in[0];
    const float* lat = (const float*)d_in[1];
    const void*  eix = d_in[2];
    const void*  e2g = d_in[3];
    const float* fd  = (const float*)d_in[4];
    const float* gam = (const float*)d_in[6];
    const float* bet = (const float*)d_in[7];
    const float* We1 = (const float*)d_in[8];
    const float* be1 = (const float*)d_in[9];
    const float* We2 = (const float*)d_in[10];
    const float* be2 = (const float*)d_in[11];
    const float* Wn1 = (const float*)d_in[12];
    const float* bn1 = (const float*)d_in[13];
    const float* Wn2 = (const float*)d_in[14];
    const float* bn2 = (const float*)d_in[15];
    float* out = (float*)d_out;

    const int Nn = in_sizes[0] / H;
    const int Gn = in_sizes[1] / 9;
    const int E  = in_sizes[4] / 3;
    const dim3 gN(1, (Nn + 63) / 64);
    const dim3 gN3(3, (Nn + 63) / 64);   // merged P|Q|S, N=768
    const dim3 gE(1, (E + 63) / 64);

    // ---- fork ----
    cudaEventRecord(evFork, 0);
    cudaStreamWaitEvent(s1, evFork, 0);
    cudaStreamWaitEvent(s2, evFork, 0);

    // s1: layernorm (feeds GEMM0)
    ln_k<<<Nn, 256, 0, s1>>>(nf, gam, bet);
    cudaEventRecord(evS1, s1);

    // s2: index conversion + degree counts + lattice fold
    cudaMemsetAsync(p_sums, 0, (size_t)Nn * H * sizeof(float), s2);
    cudaMemsetAsync(p_cnt, 0, (size_t)Nn * sizeof(float), s2);
    detect_k<<<1, 256, 0, s2>>>(eix, E);
    convert_k<<<(E + 255) / 256, 256, 0, s2>>>(eix, e2g, E);
    rcnt_k<<<(Nn + 255) / 256, 256, 0, s2>>>(Nn);
    lat_k<<<Gn, 256, 0, s2>>>(lat, We1, be1);
    cudaEventRecord(evS2, s2);

    // s0: weight transpose, then PQS precompute (after ln)
    twall_k<<<dim3(384, 7), 256>>>(We1, We2, Wn1, Wn2,
                                   p_wPQS, p_wF, p_w2, p_wN, p_wO);
    cudaStreamWaitEvent(0, evS1, 0);
    tgemm<0, 0><<<gN3, 256, SMEM_TOTAL>>>(p_hs, p_wPQS, Nn, 256, 768,
                                          0, 0, 0, 0, 0, 0, 0, 0, 0, 0, p_PQS, 0);

    // ---- join ----
    cudaStreamWaitEvent(0, evS2, 0);

    // edge layer 1 (A generated in-kernel from frac_diff):
    // e1 = silu(sinemb(fd)@Wf + P[src] + Q[dst] + R[e2g]) -> fp16
    tgemm<1, 1><<<gE, 256, SMEM_TOTAL>>>(0, p_wF, E, 384, 768,
                                         p_src, p_dst, p_e2g, p_PQS, p_PQS + 256, p_R,
                                         0, 0, 0, fd, 0, p_e1);

    // edge layer 2 + scatter: sums[src] += silu(e1@We2 + be2)  (red.v2)
    tgemm<2, 0><<<gE, 256, SMEM_TOTAL>>>(p_e1, p_w2, E, 256, 256,
                                         p_src, 0, 0, 0, 0, 0,
                                         be2, 0, 0, 0, p_sums, 0);

    cvt_k<<<(Nn * H + 255) / 256, 256>>>(p_sums, p_sum16, Nn * H);

    // node layer 1: t1 = silu(rcnt*(sums@Wn1b) + S + bn1) -> fp16
    tgemm<3, 0><<<gN, 256, SMEM_TOTAL>>>(p_sum16, p_wN, Nn, 256, 768,
                                         0, 0, 0, 0, 0, 0,
                                         bn1, p_rcnt, p_PQS + 512, 0, 0, p_t1);

    // node layer 2 + residual: out = nf + silu(t1@Wn2 + bn2)
    tgemm<4, 0><<<gN, 256, SMEM_TOTAL>>>(p_t1, p_wO, Nn, 256, 256,
                                         0, 0, 0, 0, 0, 0,
                                         bn2, 0, nf, 0, out, 0);
}

// round 16
// speedup vs baseline: 1.0779x; 1.0779x over previous
#include <cuda_runtime.h>
#include <cuda_fp16.h>
#include <cstdint>

#define H 256
#define NMAX 20000
#define EMAX 320000
#define GMAX 1000
#define DIS 384

typedef unsigned int u32;
typedef unsigned short us;

// ============================ helpers ============================
__device__ __forceinline__ u32 smem_u32(const void* p) {
    u32 a;
    asm("{ .reg .u64 t; cvta.to.shared.u64 t, %1; cvt.u32.u64 %0, t; }" : "=r"(a) : "l"(p));
    return a;
}
__device__ __forceinline__ void cpa(u32 dst, const void* src, int sz) {
    asm volatile("cp.async.cg.shared.global [%0], [%1], 16, %2;"
                 :: "r"(dst), "l"(src), "r"(sz) : "memory");
}
__device__ __forceinline__ void cpcommit() {
    asm volatile("cp.async.commit_group;" ::: "memory");
}
template <int N>
__device__ __forceinline__ void cpwait() {
    asm volatile("cp.async.wait_group %0;" :: "n"(N) : "memory");
}
__device__ __forceinline__ void ldmx4(u32* r, u32 addr) {
    asm volatile("ldmatrix.sync.aligned.m8n8.x4.shared.b16 {%0,%1,%2,%3}, [%4];"
                 : "=r"(r[0]), "=r"(r[1]), "=r"(r[2]), "=r"(r[3]) : "r"(addr));
}
// m16n8k16 fp16 mma, fp32 accum (arch-neutral HMMA path)
__device__ __forceinline__ void mma16816(float* c, const u32* a, const u32* b) {
    asm volatile(
        "mma.sync.aligned.m16n8k16.row.col.f32.f16.f16.f32 "
        "{%0,%1,%2,%3},{%4,%5,%6,%7},{%8,%9},{%0,%1,%2,%3};"
        : "+f"(c[0]), "+f"(c[1]), "+f"(c[2]), "+f"(c[3])
        : "r"(a[0]), "r"(a[1]), "r"(a[2]), "r"(a[3]), "r"(b[0]), "r"(b[1]));
}
// vector fp32 reduction (PTX ISA 8.1+, sm_90+; validated rounds 10-15)
__device__ __forceinline__ void redv2(float* addr, float a, float b) {
    asm volatile("red.global.add.v2.f32 [%0], {%1, %2};"
                 :: "l"(addr), "f"(a), "f"(b) : "memory");
}
__device__ __forceinline__ float dsilu(float x) {
    return __fdividef(x, 1.0f + __expf(-x));
}
__device__ __forceinline__ us cvt1(float v) {
    __half h = __float2half(v);
    return *reinterpret_cast<us*>(&h);
}
__device__ __forceinline__ float2 h2f2(u32 w) {
    __half2 h = *reinterpret_cast<__half2*>(&w);
    return __half22float2(h);
}

// ============================ device scratch ============================
__device__ int g_is64;
__device__ int g_src[EMAX];
__device__ int g_dst[EMAX];
__device__ int g_e2g[EMAX];
__device__ us g_PQS[(size_t)NMAX * 768];  // P | Q | S per row (fp16)
__device__ us g_R[GMAX * H];              // fp16
__device__ float g_sums[NMAX * H];
__device__ float g_cnt[NMAX];
__device__ float g_rcnt[NMAX];
// fp16 activations
__device__ us g_hs[NMAX * H];
__device__ us g_e1[(size_t)EMAX * H];
__device__ us g_t1[NMAX * H];
// fp16 transposed weights Bt[n][k]
__device__ us g_wPQS[768 * H];
__device__ us g_wF[H * DIS];   // femb weights, K PERMUTED: k' = d*128 + 2f + s
__device__ us g_w2[H * H];
__device__ us g_wN[H * H];
__device__ us g_wO[H * H];

// ============================ small kernels ============================
__global__ void detect_k(const void* eidx, int E) {
    __shared__ int any;
    if (threadIdx.x == 0) any = 0;
    __syncthreads();
    const int* w = (const int*)eidx;
    int lim = 2048 < (E - 1) ? 2048 : (E - 1);
    for (int i = threadIdx.x; i < lim; i += blockDim.x)
        if (w[2 * i + 1] != 0) any = 1;
    __syncthreads();
    if (threadIdx.x == 0) g_is64 = (any == 0) ? 1 : 0;
}

__global__ void convert_k(const void* eidx, const void* e2g, int E) {
    int i = blockIdx.x * blockDim.x + threadIdx.x;
    if (i >= E) return;
    int s;
    if (g_is64) {
        const long long* p = (const long long*)eidx;
        const long long* q = (const long long*)e2g;
        s = (int)p[i];
        g_dst[i] = (int)p[(size_t)E + i];
        g_e2g[i] = (int)q[i];
    } else {
        const int* p = (const int*)eidx;
        const int* q = (const int*)e2g;
        s = p[i];
        g_dst[i] = p[E + i];
        g_e2g[i] = q[i];
    }
    g_src[i] = s;
    atomicAdd(&g_cnt[s], 1.0f);
}

__global__ void rcnt_k(int Nn) {
    int i = blockIdx.x * blockDim.x + threadIdx.x;
    if (i < Nn) g_rcnt[i] = 1.0f / fmaxf(g_cnt[i], 1.0f);
}

__global__ __launch_bounds__(256) void ln_k(const float* __restrict__ x,
                                            const float* __restrict__ gm,
                                            const float* __restrict__ bt) {
    int row = blockIdx.x;
    int c = threadIdx.x;
    float v = x[(size_t)row * H + c];
    float s = v, ss = v * v;
#pragma unroll
    for (int o = 16; o; o >>= 1) {
        s  += __shfl_xor_sync(0xffffffffu, s, o);
        ss += __shfl_xor_sync(0xffffffffu, ss, o);
    }
    __shared__ float as[8], bs[8];
    if ((c & 31) == 0) { as[c >> 5] = s; bs[c >> 5] = ss; }
    __syncthreads();
    s = 0.f; ss = 0.f;
#pragma unroll
    for (int i = 0; i < 8; i++) { s += as[i]; ss += bs[i]; }
    float mu  = s * (1.0f / H);
    float var = ss * (1.0f / H) - mu * mu;
    float inv = rsqrtf(var + 1e-5f);
    g_hs[(size_t)row * H + c] = cvt1((v - mu) * inv * gm[c] + bt[c]);
}

__global__ __launch_bounds__(256) void lat_k(const float* __restrict__ L,
                                             const float* __restrict__ We1,
                                             const float* __restrict__ be1) {
    int g = blockIdx.x;
    __shared__ float ll[9];
    if (threadIdx.x < 9) {
        int i = threadIdx.x / 3, k = threadIdx.x % 3;
        const float* Lg = L + g * 9;
        ll[threadIdx.x] = Lg[i * 3 + 0] * Lg[k * 3 + 0] +
                          Lg[i * 3 + 1] * Lg[k * 3 + 1] +
                          Lg[i * 3 + 2] * Lg[k * 3 + 2];
    }
    __syncthreads();
    int c = threadIdx.x;
    float a = be1[c];
#pragma unroll
    for (int p = 0; p < 9; p++) a += ll[p] * We1[(512 + p) * H + c];
    g_R[g * H + c] = cvt1(a);
}

// merged weight transpose -> fp16 for all 7 segments: Bt[n][k] = fp16(W[k][n])
// Segment 3 (femb) applies the K-permutation k' = d*128 + 2f + s.
__global__ void twall_k(const float* __restrict__ We1, const float* __restrict__ We2,
                        const float* __restrict__ Wn1, const float* __restrict__ Wn2,
                        us* __restrict__ wPQS, us* __restrict__ wF,
                        us* __restrict__ w2, us* __restrict__ wN, us* __restrict__ wO) {
    const int seg = blockIdx.y;
    const int idx = blockIdx.x * 256 + threadIdx.x;
    const float* W;
    int K;
    us* o;
    switch (seg) {
        case 0: W = We1;           K = 256; o = wPQS;           break;  // P
        case 1: W = We1 + 256 * H; K = 256; o = wPQS + 256 * H; break;  // Q
        case 2: W = Wn1;           K = 256; o = wPQS + 512 * H; break;  // S
        case 3: W = We1 + 521 * H; K = 384; o = wF;             break;  // femb (permuted)
        case 4: W = We2;           K = 256; o = w2;             break;
        case 5: W = Wn1 + 256 * H; K = 256; o = wN;             break;
        default: W = Wn2;          K = 256; o = wO;             break;
    }
    if (idx >= 256 * K) return;
    int n = idx / K, k = idx % K;
    if (seg == 3) {
        int d = k >> 7, rr = k & 127, f = rr >> 1, s = rr & 1;
        k = s * 192 + d * 64 + f;  // original row in We1[521:905]
    }
    o[idx] = cvt1(W[(size_t)k * 256 + n]);
}

// ============================ HMMA GEMM (fp16, 3-stage pipeline) ============
// Block tile 128(M) x 128(N), 8 warps (4M x 2N), warp tile 32x64, 2 CTAs/SM.
// A, B single fp16 planes; 1 MMA per (mt,nt) k-step; fp32 accum.
// cp.async TRIPLE-buffered KC=32 chunks; fragments via ldmatrix.x4.
// GEN=0: load fp16 A.  GEN=1: generate sinusoid A (permuted K).
// GEN=2: load fp32 from fsrc, convert to fp16 in-kernel.
// MODE 0: Ch[row*ldx+col] = fp16(acc)
// MODE 1: Ch = fp16(silu(acc + P[src] + Q[dst] + R[e2g]))   (P/Q/R fp16)
// MODE 2: red.v2(Cf[src[row]], silu(acc + bias))
// MODE 3: Ch = fp16(silu(rowScale[row]*acc + addH + bias))  (addH fp16, ldx)
// MODE 4: Cf = addRow + silu(acc + bias)                    (addRow fp32)
#define PLANE 10240       // 128 * 20 words * 4B
#define BUFB  20480       // 2 planes (A, B)
#define SMEM_TOTAL 61440  // 3 buffers

template <int MODE, int GEN>
__global__ __launch_bounds__(256, 2) void tgemm(
    const us* __restrict__ A, const us* __restrict__ B,
    int M, int K, int ldx,
    const int* __restrict__ src, const int* __restrict__ dst,
    const int* __restrict__ e2g,
    const us* __restrict__ Pm, const us* __restrict__ Qm,
    const us* __restrict__ Rm,
    const float* __restrict__ bias, const float* __restrict__ rowScale,
    const us* __restrict__ addH, const float* __restrict__ addRow,
    const float* __restrict__ fsrc,
    float* __restrict__ Cf, us* __restrict__ Ch) {
    extern __shared__ char smem[];
    const u32 sb = smem_u32(smem);
    const int tid  = threadIdx.x;
    const int lane = tid & 31;
    const int wid  = tid >> 5;
    const int g = lane >> 2, q = lane & 3;
    const int row0  = blockIdx.y * 128;
    const int nbase = blockIdx.x * 128;
    const int mrow0  = (wid & 3) * 32;
    const int nwarp0 = (wid >> 2) * 64;

    const int rowin = lane & 7;
    const int msel  = lane >> 3;
    u32 offA[2];  // [mt]
#pragma unroll
    for (int mt = 0; mt < 2; mt++)
        offA[mt] = (u32)((mrow0 + mt * 16 + rowin + (msel & 1) * 8) * 80 +
                         (msel >> 1) * 16);
    const u32 offB = (u32)(PLANE + (nwarp0 + (msel >> 1) * 8 + rowin) * 80 +
                           (msel & 1) * 16);

    float acc[2][8][4];
#pragma unroll
    for (int a = 0; a < 2; a++)
#pragma unroll
        for (int b = 0; b < 8; b++)
#pragma unroll
            for (int c = 0; c < 4; c++) acc[a][b][c] = 0.0f;

    const int nch = K >> 5;

    auto issue = [&](int ch, int buf) {
        char* b0p = smem + buf * BUFB;
        const u32 b0 = sb + buf * BUFB;
        if (GEN == 1) {
            // sinusoid A chunk: 128 edges x 32 halves.
            // chunk ch: d = ch/4, freqs [(ch%4)*16, +16), sin/cos interleaved.
            const int e = tid >> 1;
            const int p = tid & 1;
            const int d = ch >> 2;
            const int f0 = ((ch & 3) << 4) + (p << 3);
            const int ge = row0 + e;
            float x = (ge < M) ? fsrc[(size_t)ge * 3 + d] : 0.0f;
            float y = x * (float)f0;
            y -= floorf(y);
            float sf, cf, s1, c1;
            __sincosf(6.28318530717958647692f * y, &sf, &cf);
            __sincosf(6.28318530717958647692f * x, &s1, &c1);
            u32 w[8];
#pragma unroll
            for (int i = 0; i < 8; i++) {
                asm("cvt.rn.f16x2.f32 %0, %1, %2;" : "=r"(w[i]) : "f"(cf), "f"(sf));
                float ns = sf * c1 + cf * s1;
                float nc = cf * c1 - sf * s1;
                sf = ns;
                cf = nc;
            }
            uint4* dst4 = (uint4*)(b0p + e * 80 + p * 32);
            dst4[0] = make_uint4(w[0], w[1], w[2], w[3]);
            dst4[1] = make_uint4(w[4], w[5], w[6], w[7]);
        } else if (GEN == 2) {
            // fp32 -> fp16 convert-load: 128 rows x 32 floats from fsrc.
            const int e = tid >> 1;
            const int p = tid & 1;
            const int ge = row0 + e;
            const bool ok = (ge < M);
            const float4* sp = (const float4*)(fsrc +
                (size_t)(ok ? ge : (M - 1)) * K + ch * 32 + p * 16);
            float4 f[4];
#pragma unroll
            for (int i = 0; i < 4; i++) f[i] = sp[i];
            if (!ok) {
#pragma unroll
                for (int i = 0; i < 4; i++) f[i] = make_float4(0.f, 0.f, 0.f, 0.f);
            }
            u32 w[8];
#pragma unroll
            for (int i = 0; i < 4; i++) {
                asm("cvt.rn.f16x2.f32 %0, %1, %2;" : "=r"(w[2 * i])     : "f"(f[i].y), "f"(f[i].x));
                asm("cvt.rn.f16x2.f32 %0, %1, %2;" : "=r"(w[2 * i + 1]) : "f"(f[i].w), "f"(f[i].z));
            }
            uint4* dst4 = (uint4*)(b0p + e * 80 + p * 32);
            dst4[0] = make_uint4(w[0], w[1], w[2], w[3]);
            dst4[1] = make_uint4(w[4], w[5], w[6], w[7]);
        }
#pragma unroll
        for (int j = 0; j < 2; j++) {
            int seg = tid + j * 256;
            int r = seg >> 2, ksg = seg & 3;
            u32 dstp = b0 + (u32)(r * 80 + ksg * 16);
            if (GEN == 0) {
                int ra = row0 + r;
                int sz = (ra < M) ? 16 : 0;
                if (ra >= M) ra = M - 1;
                cpa(dstp, A + (size_t)ra * K + ch * 32 + ksg * 8, sz);
            }
            cpa(dstp + PLANE, B + (size_t)(nbase + r) * K + ch * 32 + ksg * 8, 16);
        }
        cpcommit();
    };

    issue(0, 0);
    if (nch > 1) issue(1, 1);
    int buf = 0;
    for (int ch = 0; ch < nch; ++ch) {
        if (ch + 2 < nch) issue(ch + 2, (ch + 2) % 3);
        if (ch + 2 < nch)       cpwait<2>();
        else if (ch + 1 < nch)  cpwait<1>();
        else                    cpwait<0>();
        __syncthreads();
        const u32 ab = sb + buf * BUFB;
#pragma unroll
        for (int ks = 0; ks < 2; ks++) {
            u32 afr[2][4];
#pragma unroll
            for (int mt = 0; mt < 2; mt++)
                ldmx4(afr[mt], ab + offA[mt] + ks * 32);
#pragma unroll
            for (int nt2 = 0; nt2 < 4; nt2++) {
                u32 bf[4];
                ldmx4(bf, ab + offB + nt2 * 1280 + ks * 32);
#pragma unroll
                for (int hv = 0; hv < 2; hv++) {
                    const int nt = nt2 * 2 + hv;
#pragma unroll
                    for (int mt = 0; mt < 2; mt++)
                        mma16816(acc[mt][nt], afr[mt], bf + 2 * hv);
                }
            }
        }
        __syncthreads();
        buf = (buf + 1 == 3) ? 0 : buf + 1;
    }

    // ---- epilogue ----
#pragma unroll
    for (int mt = 0; mt < 2; mt++) {
#pragma unroll
        for (int h2 = 0; h2 < 2; h2++) {
            int row = row0 + mrow0 + mt * 16 + g + h2 * 8;
            if (row >= M) continue;
            int s = 0, dn = 0, gg = 0;
            float rsc = 0.0f;
            if (MODE == 1) { s = src[row]; dn = dst[row]; gg = e2g[row]; }
            if (MODE == 2) { s = src[row]; }
            if (MODE == 3) { rsc = rowScale[row]; }
#pragma unroll
            for (int nt = 0; nt < 8; nt++) {
                int col = nbase + nwarp0 + nt * 8 + 2 * q;
                float v0 = acc[mt][nt][h2 * 2 + 0];
                float v1 = acc[mt][nt][h2 * 2 + 1];
                if (MODE == 0) {
                    us h0 = cvt1(v0), h1 = cvt1(v1);
                    *(u32*)(Ch + (size_t)row * ldx + col) = (u32)h0 | ((u32)h1 << 16);
                } else if (MODE == 1) {
                    float2 p2 = h2f2(*(const u32*)(Pm + (size_t)s  * ldx + col));
                    float2 q2 = h2f2(*(const u32*)(Qm + (size_t)dn * ldx + col));
                    float2 r2 = h2f2(*(const u32*)(Rm + (size_t)gg * 256 + col));
                    us h0 = cvt1(dsilu(v0 + p2.x + q2.x + r2.x));
                    us h1 = cvt1(dsilu(v1 + p2.y + q2.y + r2.y));
                    *(u32*)(Ch + (size_t)row * 256 + col) = (u32)h0 | ((u32)h1 << 16);
                } else if (MODE == 2) {
                    float2 b2 = *(const float2*)(bias + col);
                    redv2(Cf + (size_t)s * 256 + col,
                          dsilu(v0 + b2.x), dsilu(v1 + b2.y));
                } else if (MODE == 3) {
                    float2 b2 = *(const float2*)(bias + col);
                    float2 a2 = h2f2(*(const u32*)(addH + (size_t)row * ldx + col));
                    us h0 = cvt1(dsilu(rsc * v0 + a2.x + b2.x));
                    us h1 = cvt1(dsilu(rsc * v1 + a2.y + b2.y));
                    *(u32*)(Ch + (size_t)row * 256 + col) = (u32)h0 | ((u32)h1 << 16);
                } else {  // MODE 4
                    float2 b2 = *(const float2*)(bias + col);
                    float2 a2 = *(const float2*)(addRow + (size_t)row * 256 + col);
                    *(float2*)(Cf + (size_t)row * 256 + col) =
                        make_float2(a2.x + dsilu(v0 + b2.x), a2.y + dsilu(v1 + b2.y));
                }
            }
        }
    }
}

// ============================ host side ============================
static float *p_sums, *p_cnt, *p_rcnt;
static int *p_src, *p_dst, *p_e2g;
static us *p_PQS, *p_R, *p_hs, *p_e1, *p_t1;
static us *p_wPQS, *p_wF, *p_w2, *p_wN, *p_wO;
static cudaStream_t s1, s2;
static cudaEvent_t evFork, evS1, evS2;
static bool g_init = false;

static void init_ptrs() {
    if (g_init) return;
    g_init = true;
    cudaGetSymbolAddress((void**)&p_PQS, g_PQS);
    cudaGetSymbolAddress((void**)&p_R, g_R);
    cudaGetSymbolAddress((void**)&p_sums, g_sums);
    cudaGetSymbolAddress((void**)&p_cnt, g_cnt);
    cudaGetSymbolAddress((void**)&p_rcnt, g_rcnt);
    cudaGetSymbolAddress((void**)&p_src, g_src);
    cudaGetSymbolAddress((void**)&p_dst, g_dst);
    cudaGetSymbolAddress((void**)&p_e2g, g_e2g);
    cudaGetSymbolAddress((void**)&p_hs, g_hs);
    cudaGetSymbolAddress((void**)&p_e1, g_e1);
    cudaGetSymbolAddress((void**)&p_t1, g_t1);
    cudaGetSymbolAddress((void**)&p_wPQS, g_wPQS);
    cudaGetSymbolAddress((void**)&p_wF, g_wF);
    cudaGetSymbolAddress((void**)&p_w2, g_w2);
    cudaGetSymbolAddress((void**)&p_wN, g_wN);
    cudaGetSymbolAddress((void**)&p_wO, g_wO);
    cudaStreamCreateWithFlags(&s1, cudaStreamNonBlocking);
    cudaStreamCreateWithFlags(&s2, cudaStreamNonBlocking);
    cudaEventCreateWithFlags(&evFork, cudaEventDisableTiming);
    cudaEventCreateWithFlags(&evS1, cudaEventDisableTiming);
    cudaEventCreateWithFlags(&evS2, cudaEventDisableTiming);
    cudaFuncSetAttribute(tgemm<0, 0>, cudaFuncAttributeMaxDynamicSharedMemorySize, SMEM_TOTAL);
    cudaFuncSetAttribute(tgemm<1, 1>, cudaFuncAttributeMaxDynamicSharedMemorySize, SMEM_TOTAL);
    cudaFuncSetAttribute(tgemm<2, 0>, cudaFuncAttributeMaxDynamicSharedMemorySize, SMEM_TOTAL);
    cudaFuncSetAttribute(tgemm<3, 2>, cudaFuncAttributeMaxDynamicSharedMemorySize, SMEM_TOTAL);
    cudaFuncSetAttribute(tgemm<4, 0>, cudaFuncAttributeMaxDynamicSharedMemorySize, SMEM_TOTAL);
}
namespace {
struct Boot {
    Boot() { init_ptrs(); }
};
static Boot boot_;
}  // namespace

extern "C" void kernel_launch(void* const* d_in, const int* in_sizes, int n_in,
                              void* d_out, int out_size) {
    init_ptrs();
    const float* nf  = (const float*)d_in[0];
    const float* lat = (const float*)d_in[1];
    const void*  eix = d_in[2];
    const void*  e2g = d_in[3];
    const float* fd  = (const float*)d_in[4];
    const float* gam = (const float*)d_in[6];
    const float* bet = (const float*)d_in[7];
    const float* We1 = (const float*)d_in[8];
    const float* be1 = (const float*)d_in[9];
    const float* We2 = (const float*)d_in[10];
    const float* be2 = (const float*)d_in[11];
    const float* Wn1 = (const float*)d_in[12];
    const float* bn1 = (const float*)d_in[13];
    const float* Wn2 = (const float*)d_in[14];
    const float* bn2 = (const float*)d_in[15];
    float* out = (float*)d_out;

    const int Nn = in_sizes[0] / H;
    const int Gn = in_sizes[1] / 9;
    const int E  = in_sizes[4] / 3;
    const dim3 gN(2, (Nn + 127) / 128);
    const dim3 gN3(6, (Nn + 127) / 128);  // merged P|Q|S, N=768
    const dim3 gE(2, (E + 127) / 128);

    // ---- fork ----
    cudaEventRecord(evFork, 0);
    cudaStreamWaitEvent(s1, evFork, 0);
    cudaStreamWaitEvent(s2, evFork, 0);

    // s1: layernorm (feeds GEMM0)
    ln_k<<<Nn, 256, 0, s1>>>(nf, gam, bet);
    cudaEventRecord(evS1, s1);

    // s2: index conversion + degree counts + lattice fold
    cudaMemsetAsync(p_sums, 0, (size_t)Nn * H * sizeof(float), s2);
    cudaMemsetAsync(p_cnt, 0, (size_t)Nn * sizeof(float), s2);
    detect_k<<<1, 256, 0, s2>>>(eix, E);
    convert_k<<<(E + 255) / 256, 256, 0, s2>>>(eix, e2g, E);
    rcnt_k<<<(Nn + 255) / 256, 256, 0, s2>>>(Nn);
    lat_k<<<Gn, 256, 0, s2>>>(lat, We1, be1);
    cudaEventRecord(evS2, s2);

    // s0: weight transpose, then PQS precompute (after ln) -> fp16 PQS
    twall_k<<<dim3(384, 7), 256>>>(We1, We2, Wn1, Wn2,
                                   p_wPQS, p_wF, p_w2, p_wN, p_wO);
    cudaStreamWaitEvent(0, evS1, 0);
    tgemm<0, 0><<<gN3, 256, SMEM_TOTAL>>>(p_hs, p_wPQS, Nn, 256, 768,
                                          0, 0, 0, 0, 0, 0, 0, 0, 0, 0, 0,
                                          0, p_PQS);

    // ---- join ----
    cudaStreamWaitEvent(0, evS2, 0);

    // edge layer 1 (A generated in-kernel from frac_diff):
    // e1 = silu(sinemb(fd)@Wf + P[src] + Q[dst] + R[e2g]) -> fp16
    tgemm<1, 1><<<gE, 256, SMEM_TOTAL>>>(0, p_wF, E, 384, 768,
                                         p_src, p_dst, p_e2g,
                                         p_PQS, p_PQS + 256, p_R,
                                         0, 0, 0, 0, fd, 0, p_e1);

    // edge layer 2 + scatter: sums[src] += silu(e1@We2 + be2)  (red.v2)
    tgemm<2, 0><<<gE, 256, SMEM_TOTAL>>>(p_e1, p_w2, E, 256, 256,
                                         p_src, 0, 0, 0, 0, 0,
                                         be2, 0, 0, 0, 0, p_sums, 0);

    // node layer 1 (A = fp32 sums converted in-kernel):
    // t1 = silu(rcnt*(sums@Wn1b) + S + bn1) -> fp16
    tgemm<3, 2><<<gN, 256, SMEM_TOTAL>>>(0, p_wN, Nn, 256, 768,
                                         0, 0, 0, 0, 0, 0,
                                         bn1, p_rcnt, p_PQS + 512, 0, p_sums,
                                         0, p_t1);

    // node layer 2 + residual: out = nf + silu(t1@Wn2 + bn2)
    tgemm<4, 0><<<gN, 256, SMEM_TOTAL>>>(p_t1, p_wO, Nn, 256, 256,
                                         0, 0, 0, 0, 0, 0,
                                         bn2, 0, 0, nf, 0, out, 0);
}

// round 17
// speedup vs baseline: 1.1054x; 1.0255x over previous
#include <cuda_runtime.h>
#include <cuda_fp16.h>
#include <cstdint>

#define H 256
#define NMAX 20000
#define EMAX 320000
#define GMAX 1000
#define DIS 384

typedef unsigned int u32;
typedef unsigned short us;

// ============================ helpers ============================
__device__ __forceinline__ u32 smem_u32(const void* p) {
    u32 a;
    asm("{ .reg .u64 t; cvta.to.shared.u64 t, %1; cvt.u32.u64 %0, t; }" : "=r"(a) : "l"(p));
    return a;
}
__device__ __forceinline__ void cpa(u32 dst, const void* src, int sz) {
    asm volatile("cp.async.cg.shared.global [%0], [%1], 16, %2;"
                 :: "r"(dst), "l"(src), "r"(sz) : "memory");
}
__device__ __forceinline__ void cpcommit() {
    asm volatile("cp.async.commit_group;" ::: "memory");
}
template <int N>
__device__ __forceinline__ void cpwait() {
    asm volatile("cp.async.wait_group %0;" :: "n"(N) : "memory");
}
__device__ __forceinline__ void ldmx4(u32* r, u32 addr) {
    asm volatile("ldmatrix.sync.aligned.m8n8.x4.shared.b16 {%0,%1,%2,%3}, [%4];"
                 : "=r"(r[0]), "=r"(r[1]), "=r"(r[2]), "=r"(r[3]) : "r"(addr));
}
// m16n8k16 fp16 mma, fp32 accum (arch-neutral HMMA path)
__device__ __forceinline__ void mma16816(float* c, const u32* a, const u32* b) {
    asm volatile(
        "mma.sync.aligned.m16n8k16.row.col.f32.f16.f16.f32 "
        "{%0,%1,%2,%3},{%4,%5,%6,%7},{%8,%9},{%0,%1,%2,%3};"
        : "+f"(c[0]), "+f"(c[1]), "+f"(c[2]), "+f"(c[3])
        : "r"(a[0]), "r"(a[1]), "r"(a[2]), "r"(a[3]), "r"(b[0]), "r"(b[1]));
}
// vector fp32 reduction (PTX ISA 8.1+, sm_90+; validated rounds 10-16)
__device__ __forceinline__ void redv2(float* addr, float a, float b) {
    asm volatile("red.global.add.v2.f32 [%0], {%1, %2};"
                 :: "l"(addr), "f"(a), "f"(b) : "memory");
}
__device__ __forceinline__ float dsilu(float x) {
    return __fdividef(x, 1.0f + __expf(-x));
}
__device__ __forceinline__ us cvt1(float v) {
    __half h = __float2half(v);
    return *reinterpret_cast<us*>(&h);
}
__device__ __forceinline__ float2 h2f2(u32 w) {
    __half2 h = *reinterpret_cast<__half2*>(&w);
    return __half22float2(h);
}

// ============================ device scratch ============================
__device__ int g_is64;
__device__ int g_src[EMAX];
__device__ int g_dst[EMAX];
__device__ int g_e2g[EMAX];
__device__ us g_PQS[(size_t)NMAX * 768];  // P | Q | S per row (fp16)
__device__ us g_R[GMAX * H];              // fp16
__device__ float g_sums[NMAX * H];
__device__ float g_cnt[NMAX];
__device__ float g_rcnt[NMAX];
// fp16 activations
__device__ us g_hs[NMAX * H];
__device__ us g_e1[(size_t)EMAX * H];
__device__ us g_t1[NMAX * H];
// fp16 transposed weights Bt[n][k]
__device__ us g_wPQS[768 * H];
__device__ us g_wF[H * DIS];   // femb weights, K PERMUTED: k' = d*128 + 2f + s
__device__ us g_w2[H * H];
__device__ us g_wN[H * H];
__device__ us g_wO[H * H];

// ============================ small kernels ============================
__global__ void detect_k(const void* eidx, int E) {
    __shared__ int any;
    if (threadIdx.x == 0) any = 0;
    __syncthreads();
    const int* w = (const int*)eidx;
    int lim = 2048 < (E - 1) ? 2048 : (E - 1);
    for (int i = threadIdx.x; i < lim; i += blockDim.x)
        if (w[2 * i + 1] != 0) any = 1;
    __syncthreads();
    if (threadIdx.x == 0) g_is64 = (any == 0) ? 1 : 0;
}

__global__ void convert_k(const void* eidx, const void* e2g, int E) {
    int i = blockIdx.x * blockDim.x + threadIdx.x;
    if (i >= E) return;
    int s;
    if (g_is64) {
        const long long* p = (const long long*)eidx;
        const long long* q = (const long long*)e2g;
        s = (int)p[i];
        g_dst[i] = (int)p[(size_t)E + i];
        g_e2g[i] = (int)q[i];
    } else {
        const int* p = (const int*)eidx;
        const int* q = (const int*)e2g;
        s = p[i];
        g_dst[i] = p[E + i];
        g_e2g[i] = q[i];
    }
    g_src[i] = s;
    atomicAdd(&g_cnt[s], 1.0f);
}

__global__ void rcnt_k(int Nn) {
    int i = blockIdx.x * blockDim.x + threadIdx.x;
    if (i < Nn) g_rcnt[i] = 1.0f / fmaxf(g_cnt[i], 1.0f);
}

// layernorm: one WARP per row, 8 rows per 256-thread block
__global__ __launch_bounds__(256) void ln_k(const float* __restrict__ x,
                                            const float* __restrict__ gm,
                                            const float* __restrict__ bt, int Nn) {
    const int warp = threadIdx.x >> 5;
    const int lane = threadIdx.x & 31;
    const int row = blockIdx.x * 8 + warp;
    if (row >= Nn) return;
    const int c0 = lane * 8;
    const float4* xp = (const float4*)(x + (size_t)row * H + c0);
    float4 a = xp[0], b = xp[1];
    float s  = a.x + a.y + a.z + a.w + b.x + b.y + b.z + b.w;
    float ss = a.x * a.x + a.y * a.y + a.z * a.z + a.w * a.w +
               b.x * b.x + b.y * b.y + b.z * b.z + b.w * b.w;
#pragma unroll
    for (int o = 16; o; o >>= 1) {
        s  += __shfl_xor_sync(0xffffffffu, s, o);
        ss += __shfl_xor_sync(0xffffffffu, ss, o);
    }
    float mu  = s * (1.0f / H);
    float var = ss * (1.0f / H) - mu * mu;
    float inv = rsqrtf(var + 1e-5f);
    const float4* gp = (const float4*)(gm + c0);
    const float4* bp = (const float4*)(bt + c0);
    float4 g0 = gp[0], g1 = gp[1], b0 = bp[0], b1 = bp[1];
    us h[8];
    h[0] = cvt1((a.x - mu) * inv * g0.x + b0.x);
    h[1] = cvt1((a.y - mu) * inv * g0.y + b0.y);
    h[2] = cvt1((a.z - mu) * inv * g0.z + b0.z);
    h[3] = cvt1((a.w - mu) * inv * g0.w + b0.w);
    h[4] = cvt1((b.x - mu) * inv * g1.x + b1.x);
    h[5] = cvt1((b.y - mu) * inv * g1.y + b1.y);
    h[6] = cvt1((b.z - mu) * inv * g1.z + b1.z);
    h[7] = cvt1((b.w - mu) * inv * g1.w + b1.w);
    uint4 v = make_uint4((u32)h[0] | ((u32)h[1] << 16), (u32)h[2] | ((u32)h[3] << 16),
                         (u32)h[4] | ((u32)h[5] << 16), (u32)h[6] | ((u32)h[7] << 16));
    *(uint4*)(g_hs + (size_t)row * H + c0) = v;
}

__global__ __launch_bounds__(256) void lat_k(const float* __restrict__ L,
                                             const float* __restrict__ We1,
                                             const float* __restrict__ be1) {
    int g = blockIdx.x;
    __shared__ float ll[9];
    if (threadIdx.x < 9) {
        int i = threadIdx.x / 3, k = threadIdx.x % 3;
        const float* Lg = L + g * 9;
        ll[threadIdx.x] = Lg[i * 3 + 0] * Lg[k * 3 + 0] +
                          Lg[i * 3 + 1] * Lg[k * 3 + 1] +
                          Lg[i * 3 + 2] * Lg[k * 3 + 2];
    }
    __syncthreads();
    int c = threadIdx.x;
    float a = be1[c];
#pragma unroll
    for (int p = 0; p < 9; p++) a += ll[p] * We1[(512 + p) * H + c];
    g_R[g * H + c] = cvt1(a);
}

// merged weight transpose -> fp16 for all 7 segments: Bt[n][k] = fp16(W[k][n])
// Segment 3 (femb) applies the K-permutation k' = d*128 + 2f + s.
__global__ void twall_k(const float* __restrict__ We1, const float* __restrict__ We2,
                        const float* __restrict__ Wn1, const float* __restrict__ Wn2,
                        us* __restrict__ wPQS, us* __restrict__ wF,
                        us* __restrict__ w2, us* __restrict__ wN, us* __restrict__ wO) {
    const int seg = blockIdx.y;
    const int idx = blockIdx.x * 256 + threadIdx.x;
    const float* W;
    int K;
    us* o;
    switch (seg) {
        case 0: W = We1;           K = 256; o = wPQS;           break;  // P
        case 1: W = We1 + 256 * H; K = 256; o = wPQS + 256 * H; break;  // Q
        case 2: W = Wn1;           K = 256; o = wPQS + 512 * H; break;  // S
        case 3: W = We1 + 521 * H; K = 384; o = wF;             break;  // femb (permuted)
        case 4: W = We2;           K = 256; o = w2;             break;
        case 5: W = Wn1 + 256 * H; K = 256; o = wN;             break;
        default: W = Wn2;          K = 256; o = wO;             break;
    }
    if (idx >= 256 * K) return;
    int n = idx / K, k = idx % K;
    if (seg == 3) {
        int d = k >> 7, rr = k & 127, f = rr >> 1, s = rr & 1;
        k = s * 192 + d * 64 + f;  // original row in We1[521:905]
    }
    o[idx] = cvt1(W[(size_t)k * 256 + n]);
}

// ============================ HMMA GEMM (fp16, 4-stage pipeline) ============
// Block tile 128(M) x 128(N), 8 warps (4M x 2N), warp tile 32x64, 2 CTAs/SM.
// A, B single fp16 planes; 1 MMA per (mt,nt) k-step; fp32 accum.
// cp.async QUAD-buffered KC=32 chunks; fragments via ldmatrix.x4.
// GEN=0: load fp16 A.  GEN=1: generate sinusoid A (permuted K).
// GEN=2: load fp32 from fsrc, convert to fp16 in-kernel.
// MODE 0: Ch[row*ldx+col] = fp16(acc)
// MODE 1: Ch = fp16(silu(acc + P[src] + Q[dst] + R[e2g]))   (P/Q/R fp16)
// MODE 2: red.v2(Cf[src[row]], silu(acc + bias))
// MODE 3: Ch = fp16(silu(rowScale[row]*acc + addH + bias))  (addH fp16, ldx)
// MODE 4: Cf = addRow + silu(acc + bias)                    (addRow fp32)
#define PLANE 10240       // 128 * 20 words * 4B
#define BUFB  20480       // 2 planes (A, B)
#define SMEM_TOTAL 81920  // 4 buffers

template <int MODE, int GEN>
__global__ __launch_bounds__(256, 2) void tgemm(
    const us* __restrict__ A, const us* __restrict__ B,
    int M, int K, int ldx,
    const int* __restrict__ src, const int* __restrict__ dst,
    const int* __restrict__ e2g,
    const us* __restrict__ Pm, const us* __restrict__ Qm,
    const us* __restrict__ Rm,
    const float* __restrict__ bias, const float* __restrict__ rowScale,
    const us* __restrict__ addH, const float* __restrict__ addRow,
    const float* __restrict__ fsrc,
    float* __restrict__ Cf, us* __restrict__ Ch) {
    extern __shared__ char smem[];
    const u32 sb = smem_u32(smem);
    const int tid  = threadIdx.x;
    const int lane = tid & 31;
    const int wid  = tid >> 5;
    const int g = lane >> 2, q = lane & 3;
    const int row0  = blockIdx.y * 128;
    const int nbase = blockIdx.x * 128;
    const int mrow0  = (wid & 3) * 32;
    const int nwarp0 = (wid >> 2) * 64;

    const int rowin = lane & 7;
    const int msel  = lane >> 3;
    u32 offA[2];  // [mt]
#pragma unroll
    for (int mt = 0; mt < 2; mt++)
        offA[mt] = (u32)((mrow0 + mt * 16 + rowin + (msel & 1) * 8) * 80 +
                         (msel >> 1) * 16);
    const u32 offB = (u32)(PLANE + (nwarp0 + (msel >> 1) * 8 + rowin) * 80 +
                           (msel & 1) * 16);

    float acc[2][8][4];
#pragma unroll
    for (int a = 0; a < 2; a++)
#pragma unroll
        for (int b = 0; b < 8; b++)
#pragma unroll
            for (int c = 0; c < 4; c++) acc[a][b][c] = 0.0f;

    const int nch = K >> 5;

    auto issue = [&](int ch, int buf) {
        char* b0p = smem + buf * BUFB;
        const u32 b0 = sb + buf * BUFB;
        if (GEN == 1) {
            // sinusoid A chunk: 128 edges x 32 halves.
            // chunk ch: d = ch/4, freqs [(ch%4)*16, +16), sin/cos interleaved.
            const int e = tid >> 1;
            const int p = tid & 1;
            const int d = ch >> 2;
            const int f0 = ((ch & 3) << 4) + (p << 3);
            const int ge = row0 + e;
            float x = (ge < M) ? fsrc[(size_t)ge * 3 + d] : 0.0f;
            float y = x * (float)f0;
            y -= floorf(y);
            float sf, cf, s1, c1;
            __sincosf(6.28318530717958647692f * y, &sf, &cf);
            __sincosf(6.28318530717958647692f * x, &s1, &c1);
            u32 w[8];
#pragma unroll
            for (int i = 0; i < 8; i++) {
                asm("cvt.rn.f16x2.f32 %0, %1, %2;" : "=r"(w[i]) : "f"(cf), "f"(sf));
                float ns = sf * c1 + cf * s1;
                float nc = cf * c1 - sf * s1;
                sf = ns;
                cf = nc;
            }
            uint4* dst4 = (uint4*)(b0p + e * 80 + p * 32);
            dst4[0] = make_uint4(w[0], w[1], w[2], w[3]);
            dst4[1] = make_uint4(w[4], w[5], w[6], w[7]);
        } else if (GEN == 2) {
            // fp32 -> fp16 convert-load: 128 rows x 32 floats from fsrc.
            const int e = tid >> 1;
            const int p = tid & 1;
            const int ge = row0 + e;
            const bool ok = (ge < M);
            const float4* sp = (const float4*)(fsrc +
                (size_t)(ok ? ge : (M - 1)) * K + ch * 32 + p * 16);
            float4 f[4];
#pragma unroll
            for (int i = 0; i < 4; i++) f[i] = sp[i];
            if (!ok) {
#pragma unroll
                for (int i = 0; i < 4; i++) f[i] = make_float4(0.f, 0.f, 0.f, 0.f);
            }
            u32 w[8];
#pragma unroll
            for (int i = 0; i < 4; i++) {
                asm("cvt.rn.f16x2.f32 %0, %1, %2;" : "=r"(w[2 * i])     : "f"(f[i].y), "f"(f[i].x));
                asm("cvt.rn.f16x2.f32 %0, %1, %2;" : "=r"(w[2 * i + 1]) : "f"(f[i].w), "f"(f[i].z));
            }
            uint4* dst4 = (uint4*)(b0p + e * 80 + p * 32);
            dst4[0] = make_uint4(w[0], w[1], w[2], w[3]);
            dst4[1] = make_uint4(w[4], w[5], w[6], w[7]);
        }
#pragma unroll
        for (int j = 0; j < 2; j++) {
            int seg = tid + j * 256;
            int r = seg >> 2, ksg = seg & 3;
            u32 dstp = b0 + (u32)(r * 80 + ksg * 16);
            if (GEN == 0) {
                int ra = row0 + r;
                int sz = (ra < M) ? 16 : 0;
                if (ra >= M) ra = M - 1;
                cpa(dstp, A + (size_t)ra * K + ch * 32 + ksg * 8, sz);
            }
            cpa(dstp + PLANE, B + (size_t)(nbase + r) * K + ch * 32 + ksg * 8, 16);
        }
        cpcommit();
    };

    issue(0, 0);
    if (nch > 1) issue(1, 1);
    if (nch > 2) issue(2, 2);
    int buf = 0;
    for (int ch = 0; ch < nch; ++ch) {
        if (ch + 3 < nch) issue(ch + 3, (ch + 3) & 3);
        if (ch + 3 < nch)       cpwait<3>();
        else if (ch + 2 < nch)  cpwait<2>();
        else if (ch + 1 < nch)  cpwait<1>();
        else                    cpwait<0>();
        __syncthreads();
        const u32 ab = sb + buf * BUFB;
#pragma unroll
        for (int ks = 0; ks < 2; ks++) {
            u32 afr[2][4];
#pragma unroll
            for (int mt = 0; mt < 2; mt++)
                ldmx4(afr[mt], ab + offA[mt] + ks * 32);
#pragma unroll
            for (int nt2 = 0; nt2 < 4; nt2++) {
                u32 bf[4];
                ldmx4(bf, ab + offB + nt2 * 1280 + ks * 32);
#pragma unroll
                for (int hv = 0; hv < 2; hv++) {
                    const int nt = nt2 * 2 + hv;
#pragma unroll
                    for (int mt = 0; mt < 2; mt++)
                        mma16816(acc[mt][nt], afr[mt], bf + 2 * hv);
                }
            }
        }
        __syncthreads();
        buf = (buf + 1) & 3;
    }

    // ---- epilogue ----
#pragma unroll
    for (int mt = 0; mt < 2; mt++) {
#pragma unroll
        for (int h2 = 0; h2 < 2; h2++) {
            int row = row0 + mrow0 + mt * 16 + g + h2 * 8;
            if (row >= M) continue;
            int s = 0, dn = 0, gg = 0;
            float rsc = 0.0f;
            if (MODE == 1) { s = src[row]; dn = dst[row]; gg = e2g[row]; }
            if (MODE == 2) { s = src[row]; }
            if (MODE == 3) { rsc = rowScale[row]; }
#pragma unroll
            for (int nt = 0; nt < 8; nt++) {
                int col = nbase + nwarp0 + nt * 8 + 2 * q;
                float v0 = acc[mt][nt][h2 * 2 + 0];
                float v1 = acc[mt][nt][h2 * 2 + 1];
                if (MODE == 0) {
                    us h0 = cvt1(v0), h1 = cvt1(v1);
                    *(u32*)(Ch + (size_t)row * ldx + col) = (u32)h0 | ((u32)h1 << 16);
                } else if (MODE == 1) {
                    float2 p2 = h2f2(*(const u32*)(Pm + (size_t)s  * ldx + col));
                    float2 q2 = h2f2(*(const u32*)(Qm + (size_t)dn * ldx + col));
                    float2 r2 = h2f2(*(const u32*)(Rm + (size_t)gg * 256 + col));
                    us h0 = cvt1(dsilu(v0 + p2.x + q2.x + r2.x));
                    us h1 = cvt1(dsilu(v1 + p2.y + q2.y + r2.y));
                    *(u32*)(Ch + (size_t)row * 256 + col) = (u32)h0 | ((u32)h1 << 16);
                } else if (MODE == 2) {
                    float2 b2 = *(const float2*)(bias + col);
                    redv2(Cf + (size_t)s * 256 + col,
                          dsilu(v0 + b2.x), dsilu(v1 + b2.y));
                } else if (MODE == 3) {
                    float2 b2 = *(const float2*)(bias + col);
                    float2 a2 = h2f2(*(const u32*)(addH + (size_t)row * ldx + col));
                    us h0 = cvt1(dsilu(rsc * v0 + a2.x + b2.x));
                    us h1 = cvt1(dsilu(rsc * v1 + a2.y + b2.y));
                    *(u32*)(Ch + (size_t)row * 256 + col) = (u32)h0 | ((u32)h1 << 16);
                } else {  // MODE 4
                    float2 b2 = *(const float2*)(bias + col);
                    float2 a2 = *(const float2*)(addRow + (size_t)row * 256 + col);
                    *(float2*)(Cf + (size_t)row * 256 + col) =
                        make_float2(a2.x + dsilu(v0 + b2.x), a2.y + dsilu(v1 + b2.y));
                }
            }
        }
    }
}

// ============================ host side ============================
static float *p_sums, *p_cnt, *p_rcnt;
static int *p_src, *p_dst, *p_e2g;
static us *p_PQS, *p_R, *p_hs, *p_e1, *p_t1;
static us *p_wPQS, *p_wF, *p_w2, *p_wN, *p_wO;
static cudaStream_t s1, s2;
static cudaEvent_t evFork, evS1, evS2;
static bool g_init = false;

static void init_ptrs() {
    if (g_init) return;
    g_init = true;
    cudaGetSymbolAddress((void**)&p_PQS, g_PQS);
    cudaGetSymbolAddress((void**)&p_R, g_R);
    cudaGetSymbolAddress((void**)&p_sums, g_sums);
    cudaGetSymbolAddress((void**)&p_cnt, g_cnt);
    cudaGetSymbolAddress((void**)&p_rcnt, g_rcnt);
    cudaGetSymbolAddress((void**)&p_src, g_src);
    cudaGetSymbolAddress((void**)&p_dst, g_dst);
    cudaGetSymbolAddress((void**)&p_e2g, g_e2g);
    cudaGetSymbolAddress((void**)&p_hs, g_hs);
    cudaGetSymbolAddress((void**)&p_e1, g_e1);
    cudaGetSymbolAddress((void**)&p_t1, g_t1);
    cudaGetSymbolAddress((void**)&p_wPQS, g_wPQS);
    cudaGetSymbolAddress((void**)&p_wF, g_wF);
    cudaGetSymbolAddress((void**)&p_w2, g_w2);
    cudaGetSymbolAddress((void**)&p_wN, g_wN);
    cudaGetSymbolAddress((void**)&p_wO, g_wO);
    cudaStreamCreateWithFlags(&s1, cudaStreamNonBlocking);
    cudaStreamCreateWithFlags(&s2, cudaStreamNonBlocking);
    cudaEventCreateWithFlags(&evFork, cudaEventDisableTiming);
    cudaEventCreateWithFlags(&evS1, cudaEventDisableTiming);
    cudaEventCreateWithFlags(&evS2, cudaEventDisableTiming);
    cudaFuncSetAttribute(tgemm<0, 0>, cudaFuncAttributeMaxDynamicSharedMemorySize, SMEM_TOTAL);
    cudaFuncSetAttribute(tgemm<1, 1>, cudaFuncAttributeMaxDynamicSharedMemorySize, SMEM_TOTAL);
    cudaFuncSetAttribute(tgemm<2, 0>, cudaFuncAttributeMaxDynamicSharedMemorySize, SMEM_TOTAL);
    cudaFuncSetAttribute(tgemm<3, 2>, cudaFuncAttributeMaxDynamicSharedMemorySize, SMEM_TOTAL);
    cudaFuncSetAttribute(tgemm<4, 0>, cudaFuncAttributeMaxDynamicSharedMemorySize, SMEM_TOTAL);
}
namespace {
struct Boot {
    Boot() { init_ptrs(); }
};
static Boot boot_;
}  // namespace

extern "C" void kernel_launch(void* const* d_in, const int* in_sizes, int n_in,
                              void* d_out, int out_size) {
    init_ptrs();
    const float* nf  = (const float*)d_in[0];
    const float* lat = (const float*)d_in[1];
    const void*  eix = d_in[2];
    const void*  e2g = d_in[3];
    const float* fd  = (const float*)d_in[4];
    const float* gam = (const float*)d_in[6];
    const float* bet = (const float*)d_in[7];
    const float* We1 = (const float*)d_in[8];
    const float* be1 = (const float*)d_in[9];
    const float* We2 = (const float*)d_in[10];
    const float* be2 = (const float*)d_in[11];
    const float* Wn1 = (const float*)d_in[12];
    const float* bn1 = (const float*)d_in[13];
    const float* Wn2 = (const float*)d_in[14];
    const float* bn2 = (const float*)d_in[15];
    float* out = (float*)d_out;

    const int Nn = in_sizes[0] / H;
    const int Gn = in_sizes[1] / 9;
    const int E  = in_sizes[4] / 3;
    const dim3 gN(2, (Nn + 127) / 128);
    const dim3 gN3(6, (Nn + 127) / 128);  // merged P|Q|S, N=768
    const dim3 gE(2, (E + 127) / 128);

    // ---- fork ----
    cudaEventRecord(evFork, 0);
    cudaStreamWaitEvent(s1, evFork, 0);
    cudaStreamWaitEvent(s2, evFork, 0);

    // s1: layernorm (feeds GEMM0) — warp-per-row
    ln_k<<<(Nn + 7) / 8, 256, 0, s1>>>(nf, gam, bet, Nn);
    cudaEventRecord(evS1, s1);

    // s2: index conversion + degree counts + lattice fold
    cudaMemsetAsync(p_sums, 0, (size_t)Nn * H * sizeof(float), s2);
    cudaMemsetAsync(p_cnt, 0, (size_t)Nn * sizeof(float), s2);
    detect_k<<<1, 256, 0, s2>>>(eix, E);
    convert_k<<<(E + 255) / 256, 256, 0, s2>>>(eix, e2g, E);
    rcnt_k<<<(Nn + 255) / 256, 256, 0, s2>>>(Nn);
    lat_k<<<Gn, 256, 0, s2>>>(lat, We1, be1);
    cudaEventRecord(evS2, s2);

    // s0: weight transpose, then PQS precompute (after ln) -> fp16 PQS
    twall_k<<<dim3(384, 7), 256>>>(We1, We2, Wn1, Wn2,
                                   p_wPQS, p_wF, p_w2, p_wN, p_wO);
    cudaStreamWaitEvent(0, evS1, 0);
    tgemm<0, 0><<<gN3, 256, SMEM_TOTAL>>>(p_hs, p_wPQS, Nn, 256, 768,
                                          0, 0, 0, 0, 0, 0, 0, 0, 0, 0, 0,
                                          0, p_PQS);

    // ---- join ----
    cudaStreamWaitEvent(0, evS2, 0);

    // edge layer 1 (A generated in-kernel from frac_diff):
    // e1 = silu(sinemb(fd)@Wf + P[src] + Q[dst] + R[e2g]) -> fp16
    tgemm<1, 1><<<gE, 256, SMEM_TOTAL>>>(0, p_wF, E, 384, 768,
                                         p_src, p_dst, p_e2g,
                                         p_PQS, p_PQS + 256, p_R,
                                         0, 0, 0, 0, fd, 0, p_e1);

    // edge layer 2 + scatter: sums[src] += silu(e1@We2 + be2)  (red.v2)
    tgemm<2, 0><<<gE, 256, SMEM_TOTAL>>>(p_e1, p_w2, E, 256, 256,
                                         p_src, 0, 0, 0, 0, 0,
                                         be2, 0, 0, 0, 0, p_sums, 0);

    // node layer 1 (A = fp32 sums converted in-kernel):
    // t1 = silu(rcnt*(sums@Wn1b) + S + bn1) -> fp16
    tgemm<3, 2><<<gN, 256, SMEM_TOTAL>>>(0, p_wN, Nn, 256, 768,
                                         0, 0, 0, 0, 0, 0,
                                         bn1, p_rcnt, p_PQS + 512, 0, p_sums,
                                         0, p_t1);

    // node layer 2 + residual: out = nf + silu(t1@Wn2 + bn2)
    tgemm<4, 0><<<gN, 256, SMEM_TOTAL>>>(p_t1, p_wO, Nn, 256, 256,
                                         0, 0, 0, 0, 0, 0,
                                         bn2, 0, 0, nf, 0, out, 0);
}